// round 13
// baseline (speedup 1.0000x reference)
#include <cuda_runtime.h>

// Problem constants
constexpr int B = 256;
constexpr int T = 2048;
constexpr int D = 64;     // input dim
constexpr int H = 25;     // LSTM units
constexpr int G = 100;    // 4 gates * H
constexpr long long ROWS = (long long)B * T;   // 524288

// Scratch for layer-1 input projections: [B*T][25 units][4 gates] floats (~210 MB)
__device__ float g_xp[52428800];

// Packed fp32x2 FMA
__device__ __forceinline__ float2 ffma2(float2 a, float2 b, float2 c) {
    float2 d;
    asm("fma.rn.f32x2 %0, %1, %2, %3;"
        : "=l"(reinterpret_cast<unsigned long long &>(d))
        : "l"(reinterpret_cast<unsigned long long &>(a)),
          "l"(reinterpret_cast<unsigned long long &>(b)),
          "l"(reinterpret_cast<unsigned long long &>(c)));
    return d;
}

__device__ __forceinline__ float rcp_f(float x) {
    float r; asm("rcp.approx.f32 %0, %1;" : "=f"(r) : "f"(x)); return r;
}
__device__ __forceinline__ float sigm(float x)  { return rcp_f(1.0f + __expf(-x)); }
__device__ __forceinline__ float tanh_f(float x){ return fmaf(2.0f, rcp_f(1.0f + __expf(-2.0f * x)), -1.0f); }

// ---------------------------------------------------------------------------
// Kernel 1: layer-1 input projections (R10/R12 variant).
// g_xp[row][u*4+g] = x[row]·Wx_g[:,u] + b_g[u]
// ---------------------------------------------------------------------------
constexpr int XROWS = 64;

__global__ __launch_bounds__(256) void xproj_kernel(
    const float* __restrict__ x,
    const float* __restrict__ Wxi, const float* __restrict__ bi,
    const float* __restrict__ Wxf, const float* __restrict__ bf,
    const float* __restrict__ Wxc, const float* __restrict__ bc,
    const float* __restrict__ Wxo, const float* __restrict__ bo)
{
    __shared__ __align__(16) float Ws[D * G];      // weights, [j][c] (c = g*25+u)
    __shared__ __align__(16) float xT[D][68];      // transposed x tile

    const int tid = threadIdx.x;
    const long long row0 = (long long)blockIdx.x * XROWS;

    for (int idx = tid; idx < D * G; idx += 256) {
        int j = idx / G, c = idx % G;
        int g = c / H, u = c % H;
        const float* W = (g == 0) ? Wxi : (g == 1) ? Wxf : (g == 2) ? Wxc : Wxo;
        Ws[idx] = W[j * H + u];
    }
    for (int idx = tid; idx < XROWS * 16; idx += 256) {
        int r = idx >> 4, jq = idx & 15;
        float4 v = *reinterpret_cast<const float4*>(&x[(row0 + r) * D + jq * 4]);
        xT[jq * 4 + 0][r] = v.x;
        xT[jq * 4 + 1][r] = v.y;
        xT[jq * 4 + 2][r] = v.z;
        xT[jq * 4 + 3][r] = v.w;
    }
    __syncthreads();

    if (tid < 200) {
        const int c  = tid % G;
        const int rg = tid / G;    // row-half: 32 rows each
        const int g = c / H, u = c % H;
        const float bias = ((g == 0) ? bi : (g == 1) ? bf : (g == 2) ? bc : bo)[u];

        float2 acc[16];
        #pragma unroll
        for (int k = 0; k < 16; k++) acc[k] = make_float2(0.f, 0.f);

        #pragma unroll 4
        for (int j = 0; j < D; j++) {
            float w = Ws[j * G + c];
            float2 wp = make_float2(w, w);
            #pragma unroll
            for (int k4 = 0; k4 < 8; k4++) {       // broadcast LDS.128, 4 rows each
                float4 x4 = *reinterpret_cast<const float4*>(&xT[j][rg * 32 + k4 * 4]);
                acc[2 * k4]     = ffma2(make_float2(x4.x, x4.y), wp, acc[2 * k4]);
                acc[2 * k4 + 1] = ffma2(make_float2(x4.z, x4.w), wp, acc[2 * k4 + 1]);
            }
        }

        float* outp = &g_xp[(row0 + rg * 32) * G + (u * 4 + g)];
        #pragma unroll
        for (int k = 0; k < 16; k++) {
            outp[(2 * k)     * G] = acc[k].x + bias;
            outp[(2 * k + 1) * G] = acc[k].y + bias;
        }
    }
}

// ---------------------------------------------------------------------------
// Kernel 2: fused recurrence with superstep batching + per-element named
// barriers. Block = 512 threads = 16 warps = 8 elements, grid = 32.
//   Warp A (wid<8, el=wid)   : L1 recurrence (4 steps/superstep) + head (lag 8)
//   Warp B (wid>=8, el=wid-8): L2 recurrence (lag 4)
// h1/h2 are 8-deep smem rings; A writes half {4k..4k+3 &7} while B reads the
// other half, swap each superstep (bar.sync 1+el, 64 = the A/B pair only).
// 514 supersteps (k=0..513); every warp executes exactly 514 barriers.
// L2 bias folded into wx2 j=25 slot (h1[*][25]==1). Per SMSP: 2A+2B warps of
// 4 distinct elements -> latency overlap.
// ---------------------------------------------------------------------------
__global__ __launch_bounds__(512, 1) void lstm_kernel(
    const float* __restrict__ Whi1, const float* __restrict__ Whf1,
    const float* __restrict__ Whc1, const float* __restrict__ Who1,
    const float* __restrict__ Wxi2, const float* __restrict__ Wxf2,
    const float* __restrict__ Wxc2, const float* __restrict__ Wxo2,
    const float* __restrict__ bi2,  const float* __restrict__ bf2,
    const float* __restrict__ bc2,  const float* __restrict__ bo2,
    const float* __restrict__ Whi2, const float* __restrict__ Whf2,
    const float* __restrict__ Whc2, const float* __restrict__ Who2,
    const float* __restrict__ Wout, const float* __restrict__ bout,
    float* __restrict__ out)
{
    __shared__ __align__(16) float h1s[8][8][28];  // [elem][slot][unit]; [25]=1.0
    __shared__ __align__(16) float h2s[8][8][28];  // zeros in pads

    const int tid  = threadIdx.x;
    const int wid  = tid >> 5;
    const int lane = tid & 31;
    const int uu   = (lane < 25) ? lane : 24;
    const int role = (wid < 8) ? 0 : 1;
    const int el   = (wid < 8) ? wid : (wid - 8);
    const long long bT = (long long)(blockIdx.x * 8 + el) * T;
    const int barid = 1 + el;

    // ---- init smem rings ----
    {
        float* z1 = &h1s[0][0][0];
        float* z2 = &h2s[0][0][0];
        for (int i = tid; i < 8 * 8 * 28; i += 512) { z1[i] = 0.f; z2[i] = 0.f; }
    }
    __syncthreads();
    if (tid < 64) h1s[tid >> 3][tid & 7][25] = 1.0f;   // bias lane, every slot
    __syncthreads();

    if (role == 0) {
        // ================= Warp A: L1 recurrence + output head =================
        float2 wh[4][13];
        #pragma unroll
        for (int g = 0; g < 4; g++) {
            const float* W1 = (g == 0) ? Whi1 : (g == 1) ? Whf1 : (g == 2) ? Whc1 : Who1;
            #pragma unroll
            for (int jp = 0; jp < 13; jp++) {
                int j0 = 2 * jp, j1 = 2 * jp + 1;
                wh[g][jp].x = W1[j0 * 25 + uu];
                wh[g][jp].y = (j1 < 25) ? W1[j1 * 25 + uu] : 0.f;  // [12].y=0 pairs h1[25]=1
            }
        }
        const float wout_u = (lane < 25) ? Wout[lane] : 0.f;
        const float boV = bout[0];
        float c1 = 0.f;

        float4 qa[4], qb[4];
        #pragma unroll
        for (int i = 0; i < 4; i++)
            qa[i] = *reinterpret_cast<const float4*>(&g_xp[(bT + i) * G + uu * 4]);

        for (int k = 0; k <= 513; k++) {
            asm volatile("bar.sync %0, 64;" :: "r"(barid) : "memory");

            if (k <= 511) {
                // prefetch next superstep's xg (t = 4(k+1)+i)
                if (k <= 510) {
                    #pragma unroll
                    for (int i = 0; i < 4; i++)
                        qb[i] = *reinterpret_cast<const float4*>(
                            &g_xp[(bT + 4 * (k + 1) + i) * G + uu * 4]);
                }
                #pragma unroll
                for (int kk = 0; kk < 4; kk++) {
                    const int t = 4 * k + kk;
                    float4 xg = qa[kk];
                    const float4* hp = reinterpret_cast<const float4*>(h1s[el][(t + 7) & 7]);
                    float2 a0 = make_float2(0.f, 0.f), a1 = a0, a2 = a0, a3 = a0;
                    #pragma unroll
                    for (int jq = 0; jq < 7; jq++) {
                        float4 h4 = hp[jq];                 // broadcast LDS.128
                        float2 p0 = make_float2(h4.x, h4.y);
                        float2 p1 = make_float2(h4.z, h4.w);
                        a0 = ffma2(p0, wh[0][2 * jq], a0);
                        a1 = ffma2(p0, wh[1][2 * jq], a1);
                        a2 = ffma2(p0, wh[2][2 * jq], a2);
                        a3 = ffma2(p0, wh[3][2 * jq], a3);
                        if (2 * jq + 1 < 13) {
                            a0 = ffma2(p1, wh[0][2 * jq + 1], a0);
                            a1 = ffma2(p1, wh[1][2 * jq + 1], a1);
                            a2 = ffma2(p1, wh[2][2 * jq + 1], a2);
                            a3 = ffma2(p1, wh[3][2 * jq + 1], a3);
                        }
                    }
                    float gi = sigm  (a0.x + a0.y + xg.x);
                    float gf = sigm  (a1.x + a1.y + xg.y);
                    float gg = tanh_f(a2.x + a2.y + xg.z);
                    float go = sigm  (a3.x + a3.y + xg.w);
                    c1 = fmaf(gf, c1, gi * gg);
                    float h1v = go * tanh_f(c1);
                    if (lane < 25) h1s[el][t & 7][lane] = h1v;
                    __syncwarp();
                }
                #pragma unroll
                for (int i = 0; i < 4; i++) qa[i] = qb[i];
            }

            if (k >= 2) {   // head: s = 4(k-2)+kk, h2 written by B at superstep k-1
                #pragma unroll
                for (int kk = 0; kk < 4; kk++) {
                    const int s = 4 * (k - 2) + kk;
                    float term = h2s[el][s & 7][uu] * wout_u;
                    #pragma unroll
                    for (int m = 16; m > 0; m >>= 1)
                        term += __shfl_xor_sync(0xffffffffu, term, m);
                    if (lane == 0) out[bT + s] = sigm(term + boV);
                }
            }
        }
    } else {
        // ================= Warp B: L2 recurrence (lag 4) =================
        float2 wx[4][13], wh[4][13];   // wx[g][12].y = bias (pairs h1[25]=1)
        #pragma unroll
        for (int g = 0; g < 4; g++) {
            const float* WX = (g == 0) ? Wxi2 : (g == 1) ? Wxf2 : (g == 2) ? Wxc2 : Wxo2;
            const float* BB = (g == 0) ? bi2  : (g == 1) ? bf2  : (g == 2) ? bc2  : bo2;
            const float* W2 = (g == 0) ? Whi2 : (g == 1) ? Whf2 : (g == 2) ? Whc2 : Who2;
            #pragma unroll
            for (int jp = 0; jp < 13; jp++) {
                int j0 = 2 * jp, j1 = 2 * jp + 1;
                wx[g][jp].x = WX[j0 * 25 + uu];
                wx[g][jp].y = (j1 < 25) ? WX[j1 * 25 + uu] : ((j1 == 25) ? BB[uu] : 0.f);
                wh[g][jp].x = W2[j0 * 25 + uu];
                wh[g][jp].y = (j1 < 25) ? W2[j1 * 25 + uu] : 0.f;
            }
        }
        float c2 = 0.f;

        for (int k = 0; k <= 513; k++) {
            asm volatile("bar.sync %0, 64;" :: "r"(barid) : "memory");

            if (k >= 1 && k <= 512) {
                #pragma unroll
                for (int kk = 0; kk < 4; kk++) {
                    const int s = 4 * (k - 1) + kk;
                    const float4* hp = reinterpret_cast<const float4*>(h1s[el][s & 7]);
                    const float4* gp = reinterpret_cast<const float4*>(h2s[el][(s + 7) & 7]);
                    float2 z0 = make_float2(0.f, 0.f), z1 = z0, z2 = z0, z3 = z0;
                    #pragma unroll
                    for (int jq = 0; jq < 7; jq++) {
                        float4 h4 = hp[jq];                 // broadcast LDS.128
                        float4 g4 = gp[jq];
                        float2 p0 = make_float2(h4.x, h4.y);
                        float2 p1 = make_float2(h4.z, h4.w);
                        float2 r0 = make_float2(g4.x, g4.y);
                        float2 r1 = make_float2(g4.z, g4.w);
                        z0 = ffma2(p0, wx[0][2 * jq], z0);  z0 = ffma2(r0, wh[0][2 * jq], z0);
                        z1 = ffma2(p0, wx[1][2 * jq], z1);  z1 = ffma2(r0, wh[1][2 * jq], z1);
                        z2 = ffma2(p0, wx[2][2 * jq], z2);  z2 = ffma2(r0, wh[2][2 * jq], z2);
                        z3 = ffma2(p0, wx[3][2 * jq], z3);  z3 = ffma2(r0, wh[3][2 * jq], z3);
                        if (2 * jq + 1 < 13) {
                            z0 = ffma2(p1, wx[0][2 * jq + 1], z0);  z0 = ffma2(r1, wh[0][2 * jq + 1], z0);
                            z1 = ffma2(p1, wx[1][2 * jq + 1], z1);  z1 = ffma2(r1, wh[1][2 * jq + 1], z1);
                            z2 = ffma2(p1, wx[2][2 * jq + 1], z2);  z2 = ffma2(r1, wh[2][2 * jq + 1], z2);
                            z3 = ffma2(p1, wx[3][2 * jq + 1], z3);  z3 = ffma2(r1, wh[3][2 * jq + 1], z3);
                        }
                    }
                    float hi = sigm  (z0.x + z0.y);
                    float hf = sigm  (z1.x + z1.y);
                    float hg = tanh_f(z2.x + z2.y);
                    float ho = sigm  (z3.x + z3.y);
                    c2 = fmaf(hf, c2, hi * hg);
                    float h2v = ho * tanh_f(c2);
                    if (lane < 25) h2s[el][s & 7][lane] = h2v;
                    __syncwarp();
                }
            }
        }
    }
}

// ---------------------------------------------------------------------------
// Host launcher. Input order detected from in_sizes (validated R3..R12):
//   dict order      : x, Wout(25), bout(1), l1_*(12), l2_*(12)
//   signature order : x, l1_*(12), l2_*(12), Wout, bout
// Per-layer order: Wxi, bi, Whi, Wxf, bf, Whf, Wxc, bc, Whc, Wxo, bo, Who
// ---------------------------------------------------------------------------
extern "C" void kernel_launch(void* const* d_in, const int* in_sizes, int n_in,
                              void* d_out, int out_size) {
    const float* p[27];
    for (int i = 0; i < 27 && i < n_in; i++) p[i] = (const float*)d_in[i];
    const float* x = p[0];

    int l1, l2, iWout, ibout;
    if (n_in >= 3 && in_sizes[1] == H) {   // dict order (Wout right after x)
        iWout = 1; ibout = 2; l1 = 3; l2 = 15;
    } else {                                // reference-signature order
        l1 = 1; l2 = 13; iWout = 25; ibout = 26;
    }

    xproj_kernel<<<(int)(ROWS / XROWS), 256>>>(
        x,
        p[l1 + 0], p[l1 + 1],    // Wxi, bi
        p[l1 + 3], p[l1 + 4],    // Wxf, bf
        p[l1 + 6], p[l1 + 7],    // Wxc, bc
        p[l1 + 9], p[l1 + 10]);  // Wxo, bo

    lstm_kernel<<<B / 8, 512>>>(
        p[l1 + 2], p[l1 + 5], p[l1 + 8], p[l1 + 11],     // l1 Whi, Whf, Whc, Who
        p[l2 + 0], p[l2 + 3], p[l2 + 6], p[l2 + 9],      // l2 Wxi, Wxf, Wxc, Wxo
        p[l2 + 1], p[l2 + 4], p[l2 + 7], p[l2 + 10],     // l2 bi, bf, bc, bo
        p[l2 + 2], p[l2 + 5], p[l2 + 8], p[l2 + 11],     // l2 Whi, Whf, Whc, Who
        p[iWout], p[ibout],
        (float*)d_out);
}

// round 14
// speedup vs baseline: 1.9103x; 1.9103x over previous
#include <cuda_runtime.h>

// Problem constants
constexpr int B = 256;
constexpr int T = 2048;
constexpr int D = 64;     // input dim
constexpr int H = 25;     // LSTM units
constexpr int G = 100;    // 4 gates * H
constexpr long long ROWS = (long long)B * T;   // 524288

// Scratch for layer-1 input projections: [B*T][25 units][4 gates] floats (~210 MB)
__device__ float g_xp[52428800];

// Packed fp32x2 FMA
__device__ __forceinline__ float2 ffma2(float2 a, float2 b, float2 c) {
    float2 d;
    asm("fma.rn.f32x2 %0, %1, %2, %3;"
        : "=l"(reinterpret_cast<unsigned long long &>(d))
        : "l"(reinterpret_cast<unsigned long long &>(a)),
          "l"(reinterpret_cast<unsigned long long &>(b)),
          "l"(reinterpret_cast<unsigned long long &>(c)));
    return d;
}

__device__ __forceinline__ float rcp_f(float x) {
    float r; asm("rcp.approx.f32 %0, %1;" : "=f"(r) : "f"(x)); return r;
}
__device__ __forceinline__ float sigm(float x)  { return rcp_f(1.0f + __expf(-x)); }
__device__ __forceinline__ float tanh_f(float x){ return fmaf(2.0f, rcp_f(1.0f + __expf(-2.0f * x)), -1.0f); }

// ---------------------------------------------------------------------------
// Kernel 1: layer-1 input projections (R10/R12 variant, unchanged).
// g_xp[row][u*4+g] = x[row]·Wx_g[:,u] + b_g[u]
// ---------------------------------------------------------------------------
constexpr int XROWS = 64;

__global__ __launch_bounds__(256) void xproj_kernel(
    const float* __restrict__ x,
    const float* __restrict__ Wxi, const float* __restrict__ bi,
    const float* __restrict__ Wxf, const float* __restrict__ bf,
    const float* __restrict__ Wxc, const float* __restrict__ bc,
    const float* __restrict__ Wxo, const float* __restrict__ bo)
{
    __shared__ __align__(16) float Ws[D * G];      // weights, [j][c] (c = g*25+u)
    __shared__ __align__(16) float xT[D][68];      // transposed x tile

    const int tid = threadIdx.x;
    const long long row0 = (long long)blockIdx.x * XROWS;

    for (int idx = tid; idx < D * G; idx += 256) {
        int j = idx / G, c = idx % G;
        int g = c / H, u = c % H;
        const float* W = (g == 0) ? Wxi : (g == 1) ? Wxf : (g == 2) ? Wxc : Wxo;
        Ws[idx] = W[j * H + u];
    }
    for (int idx = tid; idx < XROWS * 16; idx += 256) {
        int r = idx >> 4, jq = idx & 15;
        float4 v = *reinterpret_cast<const float4*>(&x[(row0 + r) * D + jq * 4]);
        xT[jq * 4 + 0][r] = v.x;
        xT[jq * 4 + 1][r] = v.y;
        xT[jq * 4 + 2][r] = v.z;
        xT[jq * 4 + 3][r] = v.w;
    }
    __syncthreads();

    if (tid < 200) {
        const int c  = tid % G;
        const int rg = tid / G;    // row-half: 32 rows each
        const int g = c / H, u = c % H;
        const float bias = ((g == 0) ? bi : (g == 1) ? bf : (g == 2) ? bc : bo)[u];

        float2 acc[16];
        #pragma unroll
        for (int k = 0; k < 16; k++) acc[k] = make_float2(0.f, 0.f);

        #pragma unroll 4
        for (int j = 0; j < D; j++) {
            float w = Ws[j * G + c];
            float2 wp = make_float2(w, w);
            #pragma unroll
            for (int k4 = 0; k4 < 8; k4++) {       // broadcast LDS.128, 4 rows each
                float4 x4 = *reinterpret_cast<const float4*>(&xT[j][rg * 32 + k4 * 4]);
                acc[2 * k4]     = ffma2(make_float2(x4.x, x4.y), wp, acc[2 * k4]);
                acc[2 * k4 + 1] = ffma2(make_float2(x4.z, x4.w), wp, acc[2 * k4 + 1]);
            }
        }

        float* outp = &g_xp[(row0 + rg * 32) * G + (u * 4 + g)];
        #pragma unroll
        for (int k = 0; k < 16; k++) {
            outp[(2 * k)     * G] = acc[k].x + bias;
            outp[(2 * k + 1) * G] = acc[k].y + bias;
        }
    }
}

// ---------------------------------------------------------------------------
// Kernel 2: fused recurrence. Grid 128, block 128 = 2 elements x 2 warps.
//   Warp A (role 0): L1 recurrence + output head (lag 2). wh1 in regs.
//                    xg ring q[8] with STATIC indices (8-deep LDG prefetch —
//                    no local-memory demotion, DRAM latency fully hidden).
//   Warp B (role 1): L2 recurrence (lag 1). wx2+wh2 in regs; bias folded into
//                    wx2 j=25 slot (h1[*][25]==1.0).
// Per-element named barrier (bar.sync 1+el, 64), one per step; both warps
// execute exactly (T+8) barriers. Parity double-buffered h1/h2:
//   iter t: A writes h1[t&1], reads h1[(t+1)&1]; B (s=t-1) reads h1[s&1],
//   writes h2[s&1], reads own h2[(s+1)&1]; head (s'=t-2) reads h2[t&1]. No
//   slot collisions. Split accumulator chains shorten serial latency.
// ---------------------------------------------------------------------------
struct __align__(16) ElemS {
    float h1[2][28];   // [parity][unit]; [25]=1.0 (bias lane), [26..27]=0
    float h2[2][28];   // [25..27]=0
};

__global__ __launch_bounds__(128, 1) void lstm_kernel(
    const float* __restrict__ Whi1, const float* __restrict__ Whf1,
    const float* __restrict__ Whc1, const float* __restrict__ Who1,
    const float* __restrict__ Wxi2, const float* __restrict__ Wxf2,
    const float* __restrict__ Wxc2, const float* __restrict__ Wxo2,
    const float* __restrict__ bi2,  const float* __restrict__ bf2,
    const float* __restrict__ bc2,  const float* __restrict__ bo2,
    const float* __restrict__ Whi2, const float* __restrict__ Whf2,
    const float* __restrict__ Whc2, const float* __restrict__ Who2,
    const float* __restrict__ Wout, const float* __restrict__ bout,
    float* __restrict__ out)
{
    __shared__ ElemS se[2];

    const int tid  = threadIdx.x;
    const int wid  = tid >> 5;
    const int lane = tid & 31;
    const int uu   = (lane < 25) ? lane : 24;
    const int el   = wid >> 1;          // element within block
    const int role = wid & 1;           // 0 = A (L1 + head), 1 = B (L2)
    const long long bT = (long long)(blockIdx.x * 2 + el) * T;
    const int barid = 1 + el;           // private barrier per element

    // ---- init smem ----
    {
        float* sz = reinterpret_cast<float*>(se);
        for (int i = tid; i < (int)(2 * sizeof(ElemS) / 4); i += 128) sz[i] = 0.f;
    }
    __syncthreads();
    if (tid < 2) { se[tid].h1[0][25] = 1.0f; se[tid].h1[1][25] = 1.0f; }
    __syncthreads();

    if (role == 0) {
        // ================= Warp A: L1 recurrence + head =================
        float2 wh[4][13];
        #pragma unroll
        for (int g = 0; g < 4; g++) {
            const float* W1 = (g == 0) ? Whi1 : (g == 1) ? Whf1 : (g == 2) ? Whc1 : Who1;
            #pragma unroll
            for (int jp = 0; jp < 13; jp++) {
                int j0 = 2 * jp, j1 = 2 * jp + 1;
                wh[g][jp].x = W1[j0 * 25 + uu];
                wh[g][jp].y = (j1 < 25) ? W1[j1 * 25 + uu] : 0.f;
            }
        }
        const float wout_u = (lane < 25) ? Wout[lane] : 0.f;
        const float boV = bout[0];
        float c1 = 0.f;

        float4 q[8];                             // STATIC-index prefetch ring
        #pragma unroll
        for (int i = 0; i < 8; i++)
            q[i] = *reinterpret_cast<const float4*>(&g_xp[(bT + i) * G + uu * 4]);

        for (int tb = 0; tb < T + 8; tb += 8) {
            #pragma unroll
            for (int k = 0; k < 8; k++) {
                const int t = tb + k;
                asm volatile("bar.sync %0, 64;" :: "r"(barid) : "memory");

                if (t < T) {
                    float4 xg = q[k];
                    if (t + 8 < T)
                        q[k] = *reinterpret_cast<const float4*>(
                            &g_xp[(bT + t + 8) * G + uu * 4]);

                    const float4* hp = reinterpret_cast<const float4*>(se[el].h1[(t + 1) & 1]);
                    // split even/odd accumulator chains (xg folded into init)
                    float2 e0 = make_float2(xg.x, 0.f), o0 = make_float2(0.f, 0.f);
                    float2 e1 = make_float2(xg.y, 0.f), o1 = o0;
                    float2 e2 = make_float2(xg.z, 0.f), o2 = o0;
                    float2 e3 = make_float2(xg.w, 0.f), o3 = o0;
                    #pragma unroll
                    for (int jq = 0; jq < 7; jq++) {
                        float4 h4 = hp[jq];               // broadcast LDS.128
                        float2 p0 = make_float2(h4.x, h4.y);
                        float2 p1 = make_float2(h4.z, h4.w);
                        e0 = ffma2(p0, wh[0][2 * jq], e0);
                        e1 = ffma2(p0, wh[1][2 * jq], e1);
                        e2 = ffma2(p0, wh[2][2 * jq], e2);
                        e3 = ffma2(p0, wh[3][2 * jq], e3);
                        if (2 * jq + 1 < 13) {
                            o0 = ffma2(p1, wh[0][2 * jq + 1], o0);
                            o1 = ffma2(p1, wh[1][2 * jq + 1], o1);
                            o2 = ffma2(p1, wh[2][2 * jq + 1], o2);
                            o3 = ffma2(p1, wh[3][2 * jq + 1], o3);
                        }
                    }
                    float gi = sigm  ((e0.x + e0.y) + (o0.x + o0.y));
                    float gf = sigm  ((e1.x + e1.y) + (o1.x + o1.y));
                    float gg = tanh_f((e2.x + e2.y) + (o2.x + o2.y));
                    float go = sigm  ((e3.x + e3.y) + (o3.x + o3.y));
                    c1 = fmaf(gf, c1, gi * gg);
                    float h1v = go * tanh_f(c1);
                    if (lane < 25) se[el].h1[t & 1][lane] = h1v;
                }

                if (t >= 2 && t <= T + 1) {        // head: s = t-2
                    const int s = t - 2;
                    float term = se[el].h2[s & 1][uu] * wout_u;   // s&1 == t&1
                    #pragma unroll
                    for (int m = 16; m > 0; m >>= 1)
                        term += __shfl_xor_sync(0xffffffffu, term, m);
                    if (lane == 0) out[bT + s] = sigm(term + boV);
                }
                __syncwarp();
            }
        }
    } else {
        // ================= Warp B: L2 recurrence (lag 1) =================
        float2 wx[4][13], wh[4][13];   // wx[g][12].y = bias (pairs h1[25]=1)
        #pragma unroll
        for (int g = 0; g < 4; g++) {
            const float* WX = (g == 0) ? Wxi2 : (g == 1) ? Wxf2 : (g == 2) ? Wxc2 : Wxo2;
            const float* BB = (g == 0) ? bi2  : (g == 1) ? bf2  : (g == 2) ? bc2  : bo2;
            const float* W2 = (g == 0) ? Whi2 : (g == 1) ? Whf2 : (g == 2) ? Whc2 : Who2;
            #pragma unroll
            for (int jp = 0; jp < 13; jp++) {
                int j0 = 2 * jp, j1 = 2 * jp + 1;
                wx[g][jp].x = WX[j0 * 25 + uu];
                wx[g][jp].y = (j1 < 25) ? WX[j1 * 25 + uu] : ((j1 == 25) ? BB[uu] : 0.f);
                wh[g][jp].x = W2[j0 * 25 + uu];
                wh[g][jp].y = (j1 < 25) ? W2[j1 * 25 + uu] : 0.f;
            }
        }
        float c2 = 0.f;

        for (int tb = 0; tb < T + 8; tb += 8) {
            #pragma unroll
            for (int k = 0; k < 8; k++) {
                const int t = tb + k;
                asm volatile("bar.sync %0, 64;" :: "r"(barid) : "memory");

                if (t >= 1 && t <= T) {
                    const int s = t - 1;
                    const float4* hp = reinterpret_cast<const float4*>(se[el].h1[s & 1]);
                    const float4* gp = reinterpret_cast<const float4*>(se[el].h2[(s + 1) & 1]);
                    // split wx / wh accumulator chains (13 deep each)
                    float2 x0 = make_float2(0.f, 0.f), x1 = x0, x2 = x0, x3 = x0;
                    float2 y0 = x0, y1 = x0, y2 = x0, y3 = x0;
                    #pragma unroll
                    for (int jq = 0; jq < 7; jq++) {
                        float4 h4 = hp[jq];               // broadcast LDS.128
                        float4 g4 = gp[jq];
                        float2 p0 = make_float2(h4.x, h4.y);
                        float2 p1 = make_float2(h4.z, h4.w);
                        float2 r0 = make_float2(g4.x, g4.y);
                        float2 r1 = make_float2(g4.z, g4.w);
                        x0 = ffma2(p0, wx[0][2 * jq], x0);  y0 = ffma2(r0, wh[0][2 * jq], y0);
                        x1 = ffma2(p0, wx[1][2 * jq], x1);  y1 = ffma2(r0, wh[1][2 * jq], y1);
                        x2 = ffma2(p0, wx[2][2 * jq], x2);  y2 = ffma2(r0, wh[2][2 * jq], y2);
                        x3 = ffma2(p0, wx[3][2 * jq], x3);  y3 = ffma2(r0, wh[3][2 * jq], y3);
                        if (2 * jq + 1 < 13) {
                            x0 = ffma2(p1, wx[0][2 * jq + 1], x0);  y0 = ffma2(r1, wh[0][2 * jq + 1], y0);
                            x1 = ffma2(p1, wx[1][2 * jq + 1], x1);  y1 = ffma2(r1, wh[1][2 * jq + 1], y1);
                            x2 = ffma2(p1, wx[2][2 * jq + 1], x2);  y2 = ffma2(r1, wh[2][2 * jq + 1], y2);
                            x3 = ffma2(p1, wx[3][2 * jq + 1], x3);  y3 = ffma2(r1, wh[3][2 * jq + 1], y3);
                        }
                    }
                    float hi = sigm  ((x0.x + x0.y) + (y0.x + y0.y));
                    float hf = sigm  ((x1.x + x1.y) + (y1.x + y1.y));
                    float hg = tanh_f((x2.x + x2.y) + (y2.x + y2.y));
                    float ho = sigm  ((x3.x + x3.y) + (y3.x + y3.y));
                    c2 = fmaf(hf, c2, hi * hg);
                    float h2v = ho * tanh_f(c2);
                    if (lane < 25) se[el].h2[s & 1][lane] = h2v;
                }
                __syncwarp();
            }
        }
    }
}

// ---------------------------------------------------------------------------
// Host launcher. Input order detected from in_sizes (validated R3..R13):
//   dict order      : x, Wout(25), bout(1), l1_*(12), l2_*(12)
//   signature order : x, l1_*(12), l2_*(12), Wout, bout
// Per-layer order: Wxi, bi, Whi, Wxf, bf, Whf, Wxc, bc, Whc, Wxo, bo, Who
// ---------------------------------------------------------------------------
extern "C" void kernel_launch(void* const* d_in, const int* in_sizes, int n_in,
                              void* d_out, int out_size) {
    const float* p[27];
    for (int i = 0; i < 27 && i < n_in; i++) p[i] = (const float*)d_in[i];
    const float* x = p[0];

    int l1, l2, iWout, ibout;
    if (n_in >= 3 && in_sizes[1] == H) {   // dict order (Wout right after x)
        iWout = 1; ibout = 2; l1 = 3; l2 = 15;
    } else {                                // reference-signature order
        l1 = 1; l2 = 13; iWout = 25; ibout = 26;
    }

    xproj_kernel<<<(int)(ROWS / XROWS), 256>>>(
        x,
        p[l1 + 0], p[l1 + 1],    // Wxi, bi
        p[l1 + 3], p[l1 + 4],    // Wxf, bf
        p[l1 + 6], p[l1 + 7],    // Wxc, bc
        p[l1 + 9], p[l1 + 10]);  // Wxo, bo

    lstm_kernel<<<B / 2, 128>>>(
        p[l1 + 2], p[l1 + 5], p[l1 + 8], p[l1 + 11],     // l1 Whi, Whf, Whc, Who
        p[l2 + 0], p[l2 + 3], p[l2 + 6], p[l2 + 9],      // l2 Wxi, Wxf, Wxc, Wxo
        p[l2 + 1], p[l2 + 4], p[l2 + 7], p[l2 + 10],     // l2 bi, bf, bc, bo
        p[l2 + 2], p[l2 + 5], p[l2 + 8], p[l2 + 11],     // l2 Whi, Whf, Whc, Who
        p[iWout], p[ibout],
        (float*)d_out);
}

// round 15
// speedup vs baseline: 3.1654x; 1.6570x over previous
#include <cuda_runtime.h>
#include <cstdint>

// Problem constants
constexpr int B = 256;
constexpr int T = 2048;
constexpr int D = 64;     // input dim
constexpr int H = 25;     // LSTM units
constexpr int G = 100;    // 4 gates * H
constexpr long long ROWS = (long long)B * T;   // 524288

// Scratch for layer-1 input projections: [B*T][25 units][4 gates] floats (~210 MB)
__device__ float g_xp[52428800];

// Packed fp32x2 FMA
__device__ __forceinline__ float2 ffma2(float2 a, float2 b, float2 c) {
    float2 d;
    asm("fma.rn.f32x2 %0, %1, %2, %3;"
        : "=l"(reinterpret_cast<unsigned long long &>(d))
        : "l"(reinterpret_cast<unsigned long long &>(a)),
          "l"(reinterpret_cast<unsigned long long &>(b)),
          "l"(reinterpret_cast<unsigned long long &>(c)));
    return d;
}

__device__ __forceinline__ float rcp_f(float x) {
    float r; asm("rcp.approx.f32 %0, %1;" : "=f"(r) : "f"(x)); return r;
}
__device__ __forceinline__ float sigm(float x)  { return rcp_f(1.0f + __expf(-x)); }
__device__ __forceinline__ float tanh_f(float x){ return fmaf(2.0f, rcp_f(1.0f + __expf(-2.0f * x)), -1.0f); }

__device__ __forceinline__ uint32_t smem_u32(const void* p) {
    uint32_t a;
    asm("{ .reg .u64 t; cvta.to.shared.u64 t, %1; cvt.u32.u64 %0, t; }" : "=r"(a) : "l"(p));
    return a;
}
// LDGSTS 16B: completion via async-group, NOT a register scoreboard slot.
__device__ __forceinline__ void cp16(uint32_t dst, const void* src) {
    asm volatile("cp.async.cg.shared.global [%0], [%1], 16;" :: "r"(dst), "l"(src) : "memory");
}
#define CP_COMMIT() asm volatile("cp.async.commit_group;" ::: "memory")
#define CP_WAIT7()  asm volatile("cp.async.wait_group 7;" ::: "memory")

// ---------------------------------------------------------------------------
// Kernel 1: layer-1 input projections (R12 variant, unchanged).
// g_xp[row][u*4+g] = x[row]·Wx_g[:,u] + b_g[u]
// ---------------------------------------------------------------------------
constexpr int XROWS = 64;

__global__ __launch_bounds__(256) void xproj_kernel(
    const float* __restrict__ x,
    const float* __restrict__ Wxi, const float* __restrict__ bi,
    const float* __restrict__ Wxf, const float* __restrict__ bf,
    const float* __restrict__ Wxc, const float* __restrict__ bc,
    const float* __restrict__ Wxo, const float* __restrict__ bo)
{
    __shared__ __align__(16) float Ws[D * G];      // weights, [j][c] (c = g*25+u)
    __shared__ __align__(16) float xT[D][68];      // transposed x tile

    const int tid = threadIdx.x;
    const long long row0 = (long long)blockIdx.x * XROWS;

    for (int idx = tid; idx < D * G; idx += 256) {
        int j = idx / G, c = idx % G;
        int g = c / H, u = c % H;
        const float* W = (g == 0) ? Wxi : (g == 1) ? Wxf : (g == 2) ? Wxc : Wxo;
        Ws[idx] = W[j * H + u];
    }
    for (int idx = tid; idx < XROWS * 16; idx += 256) {
        int r = idx >> 4, jq = idx & 15;
        float4 v = *reinterpret_cast<const float4*>(&x[(row0 + r) * D + jq * 4]);
        xT[jq * 4 + 0][r] = v.x;
        xT[jq * 4 + 1][r] = v.y;
        xT[jq * 4 + 2][r] = v.z;
        xT[jq * 4 + 3][r] = v.w;
    }
    __syncthreads();

    if (tid < 200) {
        const int c  = tid % G;
        const int rg = tid / G;    // row-half: 32 rows each
        const int g = c / H, u = c % H;
        const float bias = ((g == 0) ? bi : (g == 1) ? bf : (g == 2) ? bc : bo)[u];

        float2 acc[16];
        #pragma unroll
        for (int k = 0; k < 16; k++) acc[k] = make_float2(0.f, 0.f);

        #pragma unroll 4
        for (int j = 0; j < D; j++) {
            float w = Ws[j * G + c];
            float2 wp = make_float2(w, w);
            #pragma unroll
            for (int k4 = 0; k4 < 8; k4++) {       // broadcast LDS.128, 4 rows each
                float4 x4 = *reinterpret_cast<const float4*>(&xT[j][rg * 32 + k4 * 4]);
                acc[2 * k4]     = ffma2(make_float2(x4.x, x4.y), wp, acc[2 * k4]);
                acc[2 * k4 + 1] = ffma2(make_float2(x4.z, x4.w), wp, acc[2 * k4 + 1]);
            }
        }

        float* outp = &g_xp[(row0 + rg * 32) * G + (u * 4 + g)];
        #pragma unroll
        for (int k = 0; k < 16; k++) {
            outp[(2 * k)     * G] = acc[k].x + bias;
            outp[(2 * k + 1) * G] = acc[k].y + bias;
        }
    }
}

// ---------------------------------------------------------------------------
// Kernel 2: fused recurrence. Grid 128, block 128 = 2 elements x 2 warps.
//   Warp A (role 0): L1 recurrence + output head (lag 2). wh1 in regs.
//                    xg stream via cp.async (LDGSTS) -> smem ring, 8 deep.
//                    NO in-loop LDG: register scoreboard carries only ~29cy
//                    LDS latencies (DRAM latency cannot leak into LDS waits).
//   Warp B (role 1): L2 recurrence (lag 1). wx2+wh2 in regs; bias folded into
//                    wx2 j=25 slot (h1[*][25]==1.0).
// Per-element named barrier (bar.sync 1+el, 64), one per step; both warps
// execute exactly T+2 barriers. Parity double-buffered h1/h2 as in R12.
// ---------------------------------------------------------------------------
struct __align__(16) ElemS {
    float h1[2][28];   // [parity][unit]; [25]=1.0 (bias lane), [26..27]=0
    float h2[2][28];   // [25..27]=0
};

__global__ __launch_bounds__(128, 1) void lstm_kernel(
    const float* __restrict__ Whi1, const float* __restrict__ Whf1,
    const float* __restrict__ Whc1, const float* __restrict__ Who1,
    const float* __restrict__ Wxi2, const float* __restrict__ Wxf2,
    const float* __restrict__ Wxc2, const float* __restrict__ Wxo2,
    const float* __restrict__ bi2,  const float* __restrict__ bf2,
    const float* __restrict__ bc2,  const float* __restrict__ bo2,
    const float* __restrict__ Whi2, const float* __restrict__ Whf2,
    const float* __restrict__ Whc2, const float* __restrict__ Who2,
    const float* __restrict__ Wout, const float* __restrict__ bout,
    float* __restrict__ out)
{
    __shared__ ElemS se[2];
    __shared__ __align__(16) float4 xqs[2][8][32];   // xg ring: [elem][slot][lane]

    const int tid  = threadIdx.x;
    const int wid  = tid >> 5;
    const int lane = tid & 31;
    const int uu   = (lane < 25) ? lane : 24;
    const int el   = wid >> 1;          // element within block
    const int role = wid & 1;           // 0 = A (L1 + head), 1 = B (L2)
    const long long bT = (long long)(blockIdx.x * 2 + el) * T;
    const int barid = 1 + el;           // private barrier per element

    // ---- init smem ----
    {
        float* sz = reinterpret_cast<float*>(se);
        for (int i = tid; i < (int)(2 * sizeof(ElemS) / 4); i += 128) sz[i] = 0.f;
    }
    __syncthreads();
    if (tid < 2) { se[tid].h1[0][25] = 1.0f; se[tid].h1[1][25] = 1.0f; }
    __syncthreads();

    if (role == 0) {
        // ================= Warp A: L1 recurrence + head =================
        float2 wh[4][13];
        #pragma unroll
        for (int g = 0; g < 4; g++) {
            const float* W1 = (g == 0) ? Whi1 : (g == 1) ? Whf1 : (g == 2) ? Whc1 : Who1;
            #pragma unroll
            for (int jp = 0; jp < 13; jp++) {
                int j0 = 2 * jp, j1 = 2 * jp + 1;
                wh[g][jp].x = W1[j0 * 25 + uu];
                wh[g][jp].y = (j1 < 25) ? W1[j1 * 25 + uu] : 0.f;
            }
        }
        const float wout_u = (lane < 25) ? Wout[lane] : 0.f;
        const float boV = bout[0];
        float c1 = 0.f;

        // cp.async ring setup: each lane owns one 16B slot per ring entry
        const uint32_t dst0 = smem_u32(&xqs[el][0][lane]);
        const float* srcb = &g_xp[bT * G + uu * 4];       // step stride = G floats

        // prologue: 8 groups in flight (steps 0..7)
        #pragma unroll
        for (int i = 0; i < 8; i++) {
            cp16(dst0 + i * 512, srcb + (long long)i * G);
            CP_COMMIT();
        }

        for (int tb = 0; tb < T + 2; tb += 2) {
            #pragma unroll
            for (int k = 0; k < 2; k++) {
                const int t = tb + k;
                asm volatile("bar.sync %0, 64;" :: "r"(barid) : "memory");

                if (t < T) {
                    // issue prefetch for t+8, keep group cadence constant
                    if (t + 8 < T)
                        cp16(dst0 + ((t + 8) & 7) * 512, srcb + (long long)(t + 8) * G);
                    CP_COMMIT();
                    CP_WAIT7();              // group carrying xg_t long complete
                    float4 xg = xqs[el][t & 7][uu];   // conflict-free LDS.128

                    const float4* hp = reinterpret_cast<const float4*>(se[el].h1[(t + 1) & 1]);
                    // split even/odd accumulator chains (xg folded into init)
                    float2 e0 = make_float2(xg.x, 0.f), o0 = make_float2(0.f, 0.f);
                    float2 e1 = make_float2(xg.y, 0.f), o1 = o0;
                    float2 e2 = make_float2(xg.z, 0.f), o2 = o0;
                    float2 e3 = make_float2(xg.w, 0.f), o3 = o0;
                    #pragma unroll
                    for (int jq = 0; jq < 7; jq++) {
                        float4 h4 = hp[jq];               // broadcast LDS.128
                        float2 p0 = make_float2(h4.x, h4.y);
                        float2 p1 = make_float2(h4.z, h4.w);
                        e0 = ffma2(p0, wh[0][2 * jq], e0);
                        e1 = ffma2(p0, wh[1][2 * jq], e1);
                        e2 = ffma2(p0, wh[2][2 * jq], e2);
                        e3 = ffma2(p0, wh[3][2 * jq], e3);
                        if (2 * jq + 1 < 13) {
                            o0 = ffma2(p1, wh[0][2 * jq + 1], o0);
                            o1 = ffma2(p1, wh[1][2 * jq + 1], o1);
                            o2 = ffma2(p1, wh[2][2 * jq + 1], o2);
                            o3 = ffma2(p1, wh[3][2 * jq + 1], o3);
                        }
                    }
                    float gi = sigm  ((e0.x + e0.y) + (o0.x + o0.y));
                    float gf = sigm  ((e1.x + e1.y) + (o1.x + o1.y));
                    float gg = tanh_f((e2.x + e2.y) + (o2.x + o2.y));
                    float go = sigm  ((e3.x + e3.y) + (o3.x + o3.y));
                    c1 = fmaf(gf, c1, gi * gg);
                    float h1v = go * tanh_f(c1);
                    if (lane < 25) se[el].h1[t & 1][lane] = h1v;
                }

                if (t >= 2 && t <= T + 1) {        // head: s = t-2
                    const int s = t - 2;
                    float term = se[el].h2[s & 1][uu] * wout_u;   // s&1 == t&1
                    #pragma unroll
                    for (int m = 16; m > 0; m >>= 1)
                        term += __shfl_xor_sync(0xffffffffu, term, m);
                    if (lane == 0) out[bT + s] = sigm(term + boV);
                }
                __syncwarp();
            }
        }
    } else {
        // ================= Warp B: L2 recurrence (lag 1) =================
        float2 wx[4][13], wh[4][13];   // wx[g][12].y = bias (pairs h1[25]=1)
        #pragma unroll
        for (int g = 0; g < 4; g++) {
            const float* WX = (g == 0) ? Wxi2 : (g == 1) ? Wxf2 : (g == 2) ? Wxc2 : Wxo2;
            const float* BB = (g == 0) ? bi2  : (g == 1) ? bf2  : (g == 2) ? bc2  : bo2;
            const float* W2 = (g == 0) ? Whi2 : (g == 1) ? Whf2 : (g == 2) ? Whc2 : Who2;
            #pragma unroll
            for (int jp = 0; jp < 13; jp++) {
                int j0 = 2 * jp, j1 = 2 * jp + 1;
                wx[g][jp].x = WX[j0 * 25 + uu];
                wx[g][jp].y = (j1 < 25) ? WX[j1 * 25 + uu] : ((j1 == 25) ? BB[uu] : 0.f);
                wh[g][jp].x = W2[j0 * 25 + uu];
                wh[g][jp].y = (j1 < 25) ? W2[j1 * 25 + uu] : 0.f;
            }
        }
        float c2 = 0.f;

        for (int tb = 0; tb < T + 2; tb += 2) {
            #pragma unroll
            for (int k = 0; k < 2; k++) {
                const int t = tb + k;
                asm volatile("bar.sync %0, 64;" :: "r"(barid) : "memory");

                if (t >= 1 && t <= T) {
                    const int s = t - 1;
                    const float4* hp = reinterpret_cast<const float4*>(se[el].h1[s & 1]);
                    const float4* gp = reinterpret_cast<const float4*>(se[el].h2[(s + 1) & 1]);
                    // split wx / wh accumulator chains
                    float2 x0 = make_float2(0.f, 0.f), x1 = x0, x2 = x0, x3 = x0;
                    float2 y0 = x0, y1 = x0, y2 = x0, y3 = x0;
                    #pragma unroll
                    for (int jq = 0; jq < 7; jq++) {
                        float4 h4 = hp[jq];               // broadcast LDS.128
                        float4 g4 = gp[jq];
                        float2 p0 = make_float2(h4.x, h4.y);
                        float2 p1 = make_float2(h4.z, h4.w);
                        float2 r0 = make_float2(g4.x, g4.y);
                        float2 r1 = make_float2(g4.z, g4.w);
                        x0 = ffma2(p0, wx[0][2 * jq], x0);  y0 = ffma2(r0, wh[0][2 * jq], y0);
                        x1 = ffma2(p0, wx[1][2 * jq], x1);  y1 = ffma2(r0, wh[1][2 * jq], y1);
                        x2 = ffma2(p0, wx[2][2 * jq], x2);  y2 = ffma2(r0, wh[2][2 * jq], y2);
                        x3 = ffma2(p0, wx[3][2 * jq], x3);  y3 = ffma2(r0, wh[3][2 * jq], y3);
                        if (2 * jq + 1 < 13) {
                            x0 = ffma2(p1, wx[0][2 * jq + 1], x0);  y0 = ffma2(r1, wh[0][2 * jq + 1], y0);
                            x1 = ffma2(p1, wx[1][2 * jq + 1], x1);  y1 = ffma2(r1, wh[1][2 * jq + 1], y1);
                            x2 = ffma2(p1, wx[2][2 * jq + 1], x2);  y2 = ffma2(r1, wh[2][2 * jq + 1], y2);
                            x3 = ffma2(p1, wx[3][2 * jq + 1], x3);  y3 = ffma2(r1, wh[3][2 * jq + 1], y3);
                        }
                    }
                    float hi = sigm  ((x0.x + x0.y) + (y0.x + y0.y));
                    float hf = sigm  ((x1.x + x1.y) + (y1.x + y1.y));
                    float hg = tanh_f((x2.x + x2.y) + (y2.x + y2.y));
                    float ho = sigm  ((x3.x + x3.y) + (y3.x + y3.y));
                    c2 = fmaf(hf, c2, hi * hg);
                    float h2v = ho * tanh_f(c2);
                    if (lane < 25) se[el].h2[s & 1][lane] = h2v;
                }
                __syncwarp();
            }
        }
    }
}

// ---------------------------------------------------------------------------
// Host launcher. Input order detected from in_sizes (validated R3..R14):
//   dict order      : x, Wout(25), bout(1), l1_*(12), l2_*(12)
//   signature order : x, l1_*(12), l2_*(12), Wout, bout
// Per-layer order: Wxi, bi, Whi, Wxf, bf, Whf, Wxc, bc, Whc, Wxo, bo, Who
// ---------------------------------------------------------------------------
extern "C" void kernel_launch(void* const* d_in, const int* in_sizes, int n_in,
                              void* d_out, int out_size) {
    const float* p[27];
    for (int i = 0; i < 27 && i < n_in; i++) p[i] = (const float*)d_in[i];
    const float* x = p[0];

    int l1, l2, iWout, ibout;
    if (n_in >= 3 && in_sizes[1] == H) {   // dict order (Wout right after x)
        iWout = 1; ibout = 2; l1 = 3; l2 = 15;
    } else {                                // reference-signature order
        l1 = 1; l2 = 13; iWout = 25; ibout = 26;
    }

    xproj_kernel<<<(int)(ROWS / XROWS), 256>>>(
        x,
        p[l1 + 0], p[l1 + 1],    // Wxi, bi
        p[l1 + 3], p[l1 + 4],    // Wxf, bf
        p[l1 + 6], p[l1 + 7],    // Wxc, bc
        p[l1 + 9], p[l1 + 10]);  // Wxo, bo

    lstm_kernel<<<B / 2, 128>>>(
        p[l1 + 2], p[l1 + 5], p[l1 + 8], p[l1 + 11],     // l1 Whi, Whf, Whc, Who
        p[l2 + 0], p[l2 + 3], p[l2 + 6], p[l2 + 9],      // l2 Wxi, Wxf, Wxc, Wxo
        p[l2 + 1], p[l2 + 4], p[l2 + 7], p[l2 + 10],     // l2 bi, bf, bc, bo
        p[l2 + 2], p[l2 + 5], p[l2 + 8], p[l2 + 11],     // l2 Whi, Whf, Whc, Who
        p[iWout], p[ibout],
        (float*)d_out);
}

// round 16
// speedup vs baseline: 3.2142x; 1.0154x over previous
#include <cuda_runtime.h>
#include <cstdint>

// Problem constants
constexpr int B = 256;
constexpr int T = 2048;
constexpr int D = 64;     // input dim
constexpr int H = 25;     // LSTM units
constexpr int G = 100;    // 4 gates * H
constexpr long long ROWS = (long long)B * T;   // 524288

// Scratch: layer-1 input projections [B*T][25 units][4 gates] (~210 MB)
__device__ float g_xp[52428800];
// Scratch: layer-2 hidden states [B*T][32] (25 used; 128B rows) (~64 MB)
__device__ float g_h2[16777216];

// Packed fp32x2 FMA
__device__ __forceinline__ float2 ffma2(float2 a, float2 b, float2 c) {
    float2 d;
    asm("fma.rn.f32x2 %0, %1, %2, %3;"
        : "=l"(reinterpret_cast<unsigned long long &>(d))
        : "l"(reinterpret_cast<unsigned long long &>(a)),
          "l"(reinterpret_cast<unsigned long long &>(b)),
          "l"(reinterpret_cast<unsigned long long &>(c)));
    return d;
}

__device__ __forceinline__ float rcp_f(float x) {
    float r; asm("rcp.approx.f32 %0, %1;" : "=f"(r) : "f"(x)); return r;
}
__device__ __forceinline__ float sigm(float x)  { return rcp_f(1.0f + __expf(-x)); }
__device__ __forceinline__ float tanh_f(float x){ return fmaf(2.0f, rcp_f(1.0f + __expf(-2.0f * x)), -1.0f); }

__device__ __forceinline__ uint32_t smem_u32(const void* p) {
    uint32_t a;
    asm("{ .reg .u64 t; cvta.to.shared.u64 t, %1; cvt.u32.u64 %0, t; }" : "=r"(a) : "l"(p));
    return a;
}
// LDGSTS 16B: completion via async-group, NOT a register scoreboard slot.
__device__ __forceinline__ void cp16(uint32_t dst, const void* src) {
    asm volatile("cp.async.cg.shared.global [%0], [%1], 16;" :: "r"(dst), "l"(src) : "memory");
}
#define CP_COMMIT() asm volatile("cp.async.commit_group;" ::: "memory")
#define CP_WAIT7()  asm volatile("cp.async.wait_group 7;" ::: "memory")

// ---------------------------------------------------------------------------
// Kernel 1: layer-1 input projections, coalesced-store version.
// Thread owns (row,u): computes all 4 gate dots, writes ONE float4 to
// g_xp[row][u*4..u*4+3]. Block = 320 threads, 64 rows, 5 pairs/thread.
// ---------------------------------------------------------------------------
constexpr int XROWS = 64;

__global__ __launch_bounds__(320) void xproj_kernel(
    const float* __restrict__ x,
    const float* __restrict__ Wxi, const float* __restrict__ bi,
    const float* __restrict__ Wxf, const float* __restrict__ bf,
    const float* __restrict__ Wxc, const float* __restrict__ bc,
    const float* __restrict__ Wxo, const float* __restrict__ bo)
{
    __shared__ __align__(16) float4 Ws4[D * H];    // [j][u] = (Wi,Wf,Wc,Wo)
    __shared__ __align__(16) float  xs[XROWS][68]; // row-major x tile (pad 68)

    const int tid = threadIdx.x;
    const long long row0 = (long long)blockIdx.x * XROWS;

    // Stage combined weights: Ws4[j*25+u] = (Wxi[j,u], Wxf[j,u], Wxc[j,u], Wxo[j,u])
    for (int idx = tid; idx < D * H; idx += 320) {
        Ws4[idx] = make_float4(Wxi[idx], Wxf[idx], Wxc[idx], Wxo[idx]);
    }
    // Stage x tile row-major (coalesced float4 loads)
    for (int idx = tid; idx < XROWS * 16; idx += 320) {
        int r = idx >> 4, jq = idx & 15;
        float4 v = *reinterpret_cast<const float4*>(&x[(row0 + r) * D + jq * 4]);
        xs[r][jq * 4 + 0] = v.x;
        xs[r][jq * 4 + 1] = v.y;
        xs[r][jq * 4 + 2] = v.z;
        xs[r][jq * 4 + 3] = v.w;
    }
    __syncthreads();

    #pragma unroll
    for (int k = 0; k < 5; k++) {
        const int p = tid + k * 320;           // 0..1599
        const int row = p / 25, u = p % 25;

        float2 acc01 = make_float2(bi[u], bf[u]);
        float2 acc23 = make_float2(bc[u], bo[u]);

        #pragma unroll 2
        for (int jc = 0; jc < 4; jc++) {       // chunks of 16 j
            float xv[16];
            #pragma unroll
            for (int q = 0; q < 4; q++) {
                float4 v = *reinterpret_cast<const float4*>(&xs[row][jc * 16 + q * 4]);
                xv[q * 4 + 0] = v.x; xv[q * 4 + 1] = v.y;
                xv[q * 4 + 2] = v.z; xv[q * 4 + 3] = v.w;
            }
            #pragma unroll
            for (int jj = 0; jj < 16; jj++) {
                float4 w4 = Ws4[(jc * 16 + jj) * 25 + u];
                float2 xp = make_float2(xv[jj], xv[jj]);
                acc01 = ffma2(xp, make_float2(w4.x, w4.y), acc01);
                acc23 = ffma2(xp, make_float2(w4.z, w4.w), acc23);
            }
        }

        *reinterpret_cast<float4*>(&g_xp[(row0 + row) * G + u * 4]) =
            make_float4(acc01.x, acc01.y, acc23.x, acc23.y);
    }
}

// ---------------------------------------------------------------------------
// Kernel 2: fused recurrence. Grid 128, block 128 = 2 elements x 2 warps.
//   Warp A (role 0): L1 recurrence ONLY. wh1 in regs; xg via cp.async ring
//                    (8 deep; no in-loop LDG -> clean scoreboard).
//   Warp B (role 1): L2 recurrence (lag 1). wx2+wh2 in regs; bias folded into
//                    wx2 j=25 slot (h1[*][25]==1.0). Streams h2 to g_h2 (STG,
//                    fire-and-forget) for the separate head kernel.
// Per-element named barrier (bar.sync 1+el, 64), one per step; both warps
// execute exactly T+2 barriers. Parity double-buffered h1/h2 as in R15.
// ---------------------------------------------------------------------------
struct __align__(16) ElemS {
    float h1[2][28];   // [parity][unit]; [25]=1.0 (bias lane), [26..27]=0
    float h2[2][28];   // [25..27]=0
};

__global__ __launch_bounds__(128, 1) void lstm_kernel(
    const float* __restrict__ Whi1, const float* __restrict__ Whf1,
    const float* __restrict__ Whc1, const float* __restrict__ Who1,
    const float* __restrict__ Wxi2, const float* __restrict__ Wxf2,
    const float* __restrict__ Wxc2, const float* __restrict__ Wxo2,
    const float* __restrict__ bi2,  const float* __restrict__ bf2,
    const float* __restrict__ bc2,  const float* __restrict__ bo2,
    const float* __restrict__ Whi2, const float* __restrict__ Whf2,
    const float* __restrict__ Whc2, const float* __restrict__ Who2)
{
    __shared__ ElemS se[2];
    __shared__ __align__(16) float4 xqs[2][8][32];   // xg ring: [elem][slot][lane]

    const int tid  = threadIdx.x;
    const int wid  = tid >> 5;
    const int lane = tid & 31;
    const int uu   = (lane < 25) ? lane : 24;
    const int el   = wid >> 1;          // element within block
    const int role = wid & 1;           // 0 = A (L1), 1 = B (L2)
    const long long bT = (long long)(blockIdx.x * 2 + el) * T;
    const int barid = 1 + el;           // private barrier per element

    // ---- init smem ----
    {
        float* sz = reinterpret_cast<float*>(se);
        for (int i = tid; i < (int)(2 * sizeof(ElemS) / 4); i += 128) sz[i] = 0.f;
    }
    __syncthreads();
    if (tid < 2) { se[tid].h1[0][25] = 1.0f; se[tid].h1[1][25] = 1.0f; }
    __syncthreads();

    if (role == 0) {
        // ================= Warp A: L1 recurrence =================
        float2 wh[4][13];
        #pragma unroll
        for (int g = 0; g < 4; g++) {
            const float* W1 = (g == 0) ? Whi1 : (g == 1) ? Whf1 : (g == 2) ? Whc1 : Who1;
            #pragma unroll
            for (int jp = 0; jp < 13; jp++) {
                int j0 = 2 * jp, j1 = 2 * jp + 1;
                wh[g][jp].x = W1[j0 * 25 + uu];
                wh[g][jp].y = (j1 < 25) ? W1[j1 * 25 + uu] : 0.f;
            }
        }
        float c1 = 0.f;

        // cp.async ring setup: each lane owns one 16B slot per ring entry
        const uint32_t dst0 = smem_u32(&xqs[el][0][lane]);
        const float* srcb = &g_xp[bT * G + uu * 4];       // step stride = G floats

        // prologue: 8 groups in flight (steps 0..7)
        #pragma unroll
        for (int i = 0; i < 8; i++) {
            cp16(dst0 + i * 512, srcb + (long long)i * G);
            CP_COMMIT();
        }

        for (int tb = 0; tb < T + 2; tb += 2) {
            #pragma unroll
            for (int k = 0; k < 2; k++) {
                const int t = tb + k;
                asm volatile("bar.sync %0, 64;" :: "r"(barid) : "memory");

                if (t < T) {
                    if (t + 8 < T)
                        cp16(dst0 + ((t + 8) & 7) * 512, srcb + (long long)(t + 8) * G);
                    CP_COMMIT();
                    CP_WAIT7();              // group carrying xg_t long complete
                    float4 xg = xqs[el][t & 7][uu];   // conflict-free LDS.128

                    const float4* hp = reinterpret_cast<const float4*>(se[el].h1[(t + 1) & 1]);
                    // split even/odd accumulator chains (xg folded into init)
                    float2 e0 = make_float2(xg.x, 0.f), o0 = make_float2(0.f, 0.f);
                    float2 e1 = make_float2(xg.y, 0.f), o1 = o0;
                    float2 e2 = make_float2(xg.z, 0.f), o2 = o0;
                    float2 e3 = make_float2(xg.w, 0.f), o3 = o0;
                    #pragma unroll
                    for (int jq = 0; jq < 7; jq++) {
                        float4 h4 = hp[jq];               // broadcast LDS.128
                        float2 p0 = make_float2(h4.x, h4.y);
                        float2 p1 = make_float2(h4.z, h4.w);
                        e0 = ffma2(p0, wh[0][2 * jq], e0);
                        e1 = ffma2(p0, wh[1][2 * jq], e1);
                        e2 = ffma2(p0, wh[2][2 * jq], e2);
                        e3 = ffma2(p0, wh[3][2 * jq], e3);
                        if (2 * jq + 1 < 13) {
                            o0 = ffma2(p1, wh[0][2 * jq + 1], o0);
                            o1 = ffma2(p1, wh[1][2 * jq + 1], o1);
                            o2 = ffma2(p1, wh[2][2 * jq + 1], o2);
                            o3 = ffma2(p1, wh[3][2 * jq + 1], o3);
                        }
                    }
                    float gi = sigm  ((e0.x + e0.y) + (o0.x + o0.y));
                    float gf = sigm  ((e1.x + e1.y) + (o1.x + o1.y));
                    float gg = tanh_f((e2.x + e2.y) + (o2.x + o2.y));
                    float go = sigm  ((e3.x + e3.y) + (o3.x + o3.y));
                    c1 = fmaf(gf, c1, gi * gg);
                    float h1v = go * tanh_f(c1);
                    if (lane < 25) se[el].h1[t & 1][lane] = h1v;
                }
                __syncwarp();
            }
        }
    } else {
        // ================= Warp B: L2 recurrence (lag 1) =================
        float2 wx[4][13], wh[4][13];   // wx[g][12].y = bias (pairs h1[25]=1)
        #pragma unroll
        for (int g = 0; g < 4; g++) {
            const float* WX = (g == 0) ? Wxi2 : (g == 1) ? Wxf2 : (g == 2) ? Wxc2 : Wxo2;
            const float* BB = (g == 0) ? bi2  : (g == 1) ? bf2  : (g == 2) ? bc2  : bo2;
            const float* W2 = (g == 0) ? Whi2 : (g == 1) ? Whf2 : (g == 2) ? Whc2 : Who2;
            #pragma unroll
            for (int jp = 0; jp < 13; jp++) {
                int j0 = 2 * jp, j1 = 2 * jp + 1;
                wx[g][jp].x = WX[j0 * 25 + uu];
                wx[g][jp].y = (j1 < 25) ? WX[j1 * 25 + uu] : ((j1 == 25) ? BB[uu] : 0.f);
                wh[g][jp].x = W2[j0 * 25 + uu];
                wh[g][jp].y = (j1 < 25) ? W2[j1 * 25 + uu] : 0.f;
            }
        }
        float c2 = 0.f;

        for (int tb = 0; tb < T + 2; tb += 2) {
            #pragma unroll
            for (int k = 0; k < 2; k++) {
                const int t = tb + k;
                asm volatile("bar.sync %0, 64;" :: "r"(barid) : "memory");

                if (t >= 1 && t <= T) {
                    const int s = t - 1;
                    const float4* hp = reinterpret_cast<const float4*>(se[el].h1[s & 1]);
                    const float4* gp = reinterpret_cast<const float4*>(se[el].h2[(s + 1) & 1]);
                    // split wx / wh accumulator chains
                    float2 x0 = make_float2(0.f, 0.f), x1 = x0, x2 = x0, x3 = x0;
                    float2 y0 = x0, y1 = x0, y2 = x0, y3 = x0;
                    #pragma unroll
                    for (int jq = 0; jq < 7; jq++) {
                        float4 h4 = hp[jq];               // broadcast LDS.128
                        float4 g4 = gp[jq];
                        float2 p0 = make_float2(h4.x, h4.y);
                        float2 p1 = make_float2(h4.z, h4.w);
                        float2 r0 = make_float2(g4.x, g4.y);
                        float2 r1 = make_float2(g4.z, g4.w);
                        x0 = ffma2(p0, wx[0][2 * jq], x0);  y0 = ffma2(r0, wh[0][2 * jq], y0);
                        x1 = ffma2(p0, wx[1][2 * jq], x1);  y1 = ffma2(r0, wh[1][2 * jq], y1);
                        x2 = ffma2(p0, wx[2][2 * jq], x2);  y2 = ffma2(r0, wh[2][2 * jq], y2);
                        x3 = ffma2(p0, wx[3][2 * jq], x3);  y3 = ffma2(r0, wh[3][2 * jq], y3);
                        if (2 * jq + 1 < 13) {
                            x0 = ffma2(p1, wx[0][2 * jq + 1], x0);  y0 = ffma2(r1, wh[0][2 * jq + 1], y0);
                            x1 = ffma2(p1, wx[1][2 * jq + 1], x1);  y1 = ffma2(r1, wh[1][2 * jq + 1], y1);
                            x2 = ffma2(p1, wx[2][2 * jq + 1], x2);  y2 = ffma2(r1, wh[2][2 * jq + 1], y2);
                            x3 = ffma2(p1, wx[3][2 * jq + 1], x3);  y3 = ffma2(r1, wh[3][2 * jq + 1], y3);
                        }
                    }
                    float hi = sigm  ((x0.x + x0.y) + (y0.x + y0.y));
                    float hf = sigm  ((x1.x + x1.y) + (y1.x + y1.y));
                    float hg = tanh_f((x2.x + x2.y) + (y2.x + y2.y));
                    float ho = sigm  ((x3.x + x3.y) + (y3.x + y3.y));
                    c2 = fmaf(hf, c2, hi * hg);
                    float h2v = ho * tanh_f(c2);
                    if (lane < 25) {
                        se[el].h2[s & 1][lane] = h2v;
                        g_h2[(bT + s) * 32 + lane] = h2v;   // stream for head kernel
                    }
                }
                __syncwarp();
            }
        }
    }
}

// ---------------------------------------------------------------------------
// Kernel 3: output head.  out[row] = sigm(dot(g_h2[row][0:25], Wout) + bout)
// Block = 256 threads / 256 rows; smem-staged with 33-stride padding so the
// per-thread row reads are bank-conflict-free.
// ---------------------------------------------------------------------------
__global__ __launch_bounds__(256) void head_kernel(
    const float* __restrict__ Wout, const float* __restrict__ bout,
    float* __restrict__ out)
{
    __shared__ float hs[256][33];
    __shared__ float wo[26];

    const int tid = threadIdx.x;
    const long long row0 = (long long)blockIdx.x * 256;

    if (tid < 25) wo[tid] = Wout[tid];
    if (tid == 25) wo[25] = bout[0];

    // Coalesced load: 256 rows x 8 float4 (row stride in g_h2 = 32 floats)
    for (int idx = tid; idx < 256 * 8; idx += 256) {
        int r = idx >> 3, q = idx & 7;
        float4 v = *reinterpret_cast<const float4*>(&g_h2[(row0 + r) * 32 + q * 4]);
        hs[r][q * 4 + 0] = v.x;
        hs[r][q * 4 + 1] = v.y;
        hs[r][q * 4 + 2] = v.z;
        hs[r][q * 4 + 3] = v.w;
    }
    __syncthreads();

    float acc = wo[25];
    #pragma unroll
    for (int j = 0; j < 25; j++) acc = fmaf(hs[tid][j], wo[j], acc);
    out[row0 + tid] = sigm(acc);
}

// ---------------------------------------------------------------------------
// Host launcher. Input order detected from in_sizes (validated R3..R15):
//   dict order      : x, Wout(25), bout(1), l1_*(12), l2_*(12)
//   signature order : x, l1_*(12), l2_*(12), Wout, bout
// Per-layer order: Wxi, bi, Whi, Wxf, bf, Whf, Wxc, bc, Whc, Wxo, bo, Who
// ---------------------------------------------------------------------------
extern "C" void kernel_launch(void* const* d_in, const int* in_sizes, int n_in,
                              void* d_out, int out_size) {
    const float* p[27];
    for (int i = 0; i < 27 && i < n_in; i++) p[i] = (const float*)d_in[i];
    const float* x = p[0];

    int l1, l2, iWout, ibout;
    if (n_in >= 3 && in_sizes[1] == H) {   // dict order (Wout right after x)
        iWout = 1; ibout = 2; l1 = 3; l2 = 15;
    } else {                                // reference-signature order
        l1 = 1; l2 = 13; iWout = 25; ibout = 26;
    }

    xproj_kernel<<<(int)(ROWS / XROWS), 320>>>(
        x,
        p[l1 + 0], p[l1 + 1],    // Wxi, bi
        p[l1 + 3], p[l1 + 4],    // Wxf, bf
        p[l1 + 6], p[l1 + 7],    // Wxc, bc
        p[l1 + 9], p[l1 + 10]);  // Wxo, bo

    lstm_kernel<<<B / 2, 128>>>(
        p[l1 + 2], p[l1 + 5], p[l1 + 8], p[l1 + 11],     // l1 Whi, Whf, Whc, Who
        p[l2 + 0], p[l2 + 3], p[l2 + 6], p[l2 + 9],      // l2 Wxi, Wxf, Wxc, Wxo
        p[l2 + 1], p[l2 + 4], p[l2 + 7], p[l2 + 10],     // l2 bi, bf, bc, bo
        p[l2 + 2], p[l2 + 5], p[l2 + 8], p[l2 + 11]);    // l2 Whi, Whf, Whc, Who

    head_kernel<<<(int)(ROWS / 256), 256>>>(p[iWout], p[ibout], (float*)d_out);
}

// round 17
// speedup vs baseline: 3.9395x; 1.2257x over previous
#include <cuda_runtime.h>
#include <cstdint>

// Problem constants
constexpr int B = 256;
constexpr int T = 2048;
constexpr int D = 64;     // input dim
constexpr int H = 25;     // LSTM units
constexpr int G = 100;    // 4 gates * H
constexpr long long ROWS = (long long)B * T;   // 524288

// Scratch: layer-1 input projections [B*T][25 units][4 gates] (~210 MB)
__device__ float g_xp[52428800];
// Scratch: layer-2 hidden states [B*T][32] (25 used; 128B rows) (~64 MB)
__device__ float g_h2[16777216];

// Packed fp32x2 FMA
__device__ __forceinline__ float2 ffma2(float2 a, float2 b, float2 c) {
    float2 d;
    asm("fma.rn.f32x2 %0, %1, %2, %3;"
        : "=l"(reinterpret_cast<unsigned long long &>(d))
        : "l"(reinterpret_cast<unsigned long long &>(a)),
          "l"(reinterpret_cast<unsigned long long &>(b)),
          "l"(reinterpret_cast<unsigned long long &>(c)));
    return d;
}

__device__ __forceinline__ float rcp_f(float x) {
    float r; asm("rcp.approx.f32 %0, %1;" : "=f"(r) : "f"(x)); return r;
}
__device__ __forceinline__ float sigm(float x)  { return rcp_f(1.0f + __expf(-x)); }
__device__ __forceinline__ float tanh_f(float x){ return fmaf(2.0f, rcp_f(1.0f + __expf(-2.0f * x)), -1.0f); }

__device__ __forceinline__ uint32_t smem_u32(const void* p) {
    uint32_t a;
    asm("{ .reg .u64 t; cvta.to.shared.u64 t, %1; cvt.u32.u64 %0, t; }" : "=r"(a) : "l"(p));
    return a;
}
// LDGSTS 16B: completion via async-group, NOT a register scoreboard slot.
__device__ __forceinline__ void cp16(uint32_t dst, const void* src) {
    asm volatile("cp.async.cg.shared.global [%0], [%1], 16;" :: "r"(dst), "l"(src) : "memory");
}
#define CP_COMMIT() asm volatile("cp.async.commit_group;" ::: "memory")
#define CP_WAIT7()  asm volatile("cp.async.wait_group 7;" ::: "memory")

// ---------------------------------------------------------------------------
// Kernel 1 (v4): layer-1 input projections.
// Column-per-thread compute (broadcast x LDS.128, 1-phase weight LDS, 32 rows
// amortized per weight read) + smem-staged output (pool reused) + coalesced
// float4 copy-out. g_xp[row][u*4+g].
// ---------------------------------------------------------------------------
constexpr int XROWS = 64;

__global__ __launch_bounds__(256) void xproj_kernel(
    const float* __restrict__ x,
    const float* __restrict__ Wxi, const float* __restrict__ bi,
    const float* __restrict__ Wxf, const float* __restrict__ bf,
    const float* __restrict__ Wxc, const float* __restrict__ bc,
    const float* __restrict__ Wxo, const float* __restrict__ bo)
{
    __shared__ __align__(16) float pool[D * G];    // Ws during compute; out after
    __shared__ __align__(16) float xT[D][68];      // transposed x tile

    const int tid = threadIdx.x;
    const long long row0 = (long long)blockIdx.x * XROWS;

    // Stage combined gate weights [j][c] (c = g*25+u)
    for (int idx = tid; idx < D * G; idx += 256) {
        int j = idx / G, c = idx % G;
        int g = c / H, u = c % H;
        const float* W = (g == 0) ? Wxi : (g == 1) ? Wxf : (g == 2) ? Wxc : Wxo;
        pool[idx] = W[j * H + u];
    }
    // Stage x tile transposed (coalesced float4 loads)
    for (int idx = tid; idx < XROWS * 16; idx += 256) {
        int r = idx >> 4, jq = idx & 15;
        float4 v = *reinterpret_cast<const float4*>(&x[(row0 + r) * D + jq * 4]);
        xT[jq * 4 + 0][r] = v.x;
        xT[jq * 4 + 1][r] = v.y;
        xT[jq * 4 + 2][r] = v.z;
        xT[jq * 4 + 3][r] = v.w;
    }
    __syncthreads();

    float2 acc[16];
    int c = 0, rg = 0, u = 0, g = 0;
    if (tid < 200) {
        c  = tid % G;
        rg = tid / G;                 // row-half: 32 rows each
        g = c / H; u = c % H;
        const float bias = ((g == 0) ? bi : (g == 1) ? bf : (g == 2) ? bc : bo)[u];

        #pragma unroll
        for (int k = 0; k < 16; k++) acc[k] = make_float2(bias, bias);

        #pragma unroll 4
        for (int j = 0; j < D; j++) {
            float w = pool[j * G + c];             // 1-phase LDS (consecutive c)
            float2 wp = make_float2(w, w);
            #pragma unroll
            for (int k4 = 0; k4 < 8; k4++) {       // broadcast LDS.128, 4 rows each
                float4 x4 = *reinterpret_cast<const float4*>(&xT[j][rg * 32 + k4 * 4]);
                acc[2 * k4]     = ffma2(make_float2(x4.x, x4.y), wp, acc[2 * k4]);
                acc[2 * k4 + 1] = ffma2(make_float2(x4.z, x4.w), wp, acc[2 * k4 + 1]);
            }
        }
    }
    __syncthreads();     // all pool reads done -> reuse as output stage

    if (tid < 200) {
        const int col = u * 4 + g;
        #pragma unroll
        for (int k = 0; k < 16; k++) {
            pool[(rg * 32 + 2 * k)     * G + col] = acc[k].x;
            pool[(rg * 32 + 2 * k + 1) * G + col] = acc[k].y;
        }
    }
    __syncthreads();

    // Coalesced copy-out: 6400 floats = 1600 float4, contiguous in g_xp
    const float4* src = reinterpret_cast<const float4*>(pool);
    float4* dst = reinterpret_cast<float4*>(&g_xp[row0 * G]);
    for (int i = tid; i < 1600; i += 256) dst[i] = src[i];
}

// ---------------------------------------------------------------------------
// Kernel 2: fused recurrence, 3 warps per element. Grid 128, block 192.
//   Warp A (role 0): L1 recurrence. wh1 regs; xg via cp.async ring (8 deep).
//   Warp C (role 2): L2 input projection (lag 1): zx_s = wx2·h1_s + b2
//                    (bias folded via h1[25]==1). Writes zx float4 per unit.
//   Warp B (role 1): L2 recurrence (lag 2): wh2·h2_{s-1} + zx_s -> h2_s.
//                    Streams h2 to g_h2 (STG) for the head kernel.
// Per-element named barrier (bar.sync 1+el, 96), one per step; all 3 warps
// execute exactly T+2 barriers. All cross-warp handoffs barrier-separated:
//   h1: A writes t&1 @t; A/C read (t-1)&1 @t.        zx: C writes (t-1)&1 @t;
//   B reads (t-2)&1 @t. h2: B-only (same warp).
// Roles by wid: 0=A0,1=B0,2=C0,3=A1,4=B1,5=C1 (SMSP spread: {A0,B1},{B0,C1},
// {C0},{A1}).
// ---------------------------------------------------------------------------
struct __align__(16) ElemS {
    float  h1[2][28];   // [parity][unit]; [25]=1.0 (bias lane), [26..27]=0
    float  h2[2][28];   // [25..27]=0
    float4 zx[2][28];   // [parity][unit]: (zi,zf,zc,zo) incl. bias
};

__global__ __launch_bounds__(192, 1) void lstm_kernel(
    const float* __restrict__ Whi1, const float* __restrict__ Whf1,
    const float* __restrict__ Whc1, const float* __restrict__ Who1,
    const float* __restrict__ Wxi2, const float* __restrict__ Wxf2,
    const float* __restrict__ Wxc2, const float* __restrict__ Wxo2,
    const float* __restrict__ bi2,  const float* __restrict__ bf2,
    const float* __restrict__ bc2,  const float* __restrict__ bo2,
    const float* __restrict__ Whi2, const float* __restrict__ Whf2,
    const float* __restrict__ Whc2, const float* __restrict__ Who2)
{
    __shared__ ElemS se[2];
    __shared__ __align__(16) float4 xqs[2][8][32];   // xg ring: [elem][slot][lane]

    const int tid  = threadIdx.x;
    const int wid  = tid >> 5;
    const int lane = tid & 31;
    const int uu   = (lane < 25) ? lane : 24;
    const int el   = (wid < 3) ? 0 : 1;
    const int role = (wid < 3) ? wid : (wid - 3);   // 0=A 1=B 2=C
    const long long bT = (long long)(blockIdx.x * 2 + el) * T;
    const int barid = 1 + el;                       // private barrier per element

    // ---- init smem ----
    {
        float* sz = reinterpret_cast<float*>(se);
        for (int i = tid; i < (int)(2 * sizeof(ElemS) / 4); i += 192) sz[i] = 0.f;
    }
    __syncthreads();
    if (tid < 2) { se[tid].h1[0][25] = 1.0f; se[tid].h1[1][25] = 1.0f; }
    __syncthreads();

    if (role == 0) {
        // ================= Warp A: L1 recurrence =================
        float2 wh[4][13];
        #pragma unroll
        for (int g = 0; g < 4; g++) {
            const float* W1 = (g == 0) ? Whi1 : (g == 1) ? Whf1 : (g == 2) ? Whc1 : Who1;
            #pragma unroll
            for (int jp = 0; jp < 13; jp++) {
                int j0 = 2 * jp, j1 = 2 * jp + 1;
                wh[g][jp].x = W1[j0 * 25 + uu];
                wh[g][jp].y = (j1 < 25) ? W1[j1 * 25 + uu] : 0.f;
            }
        }
        float c1 = 0.f;

        const uint32_t dst0 = smem_u32(&xqs[el][0][lane]);
        const float* srcb = &g_xp[bT * G + uu * 4];       // step stride = G floats

        #pragma unroll
        for (int i = 0; i < 8; i++) {                     // prologue: 8 groups
            cp16(dst0 + i * 512, srcb + (long long)i * G);
            CP_COMMIT();
        }

        #pragma unroll 2
        for (int t = 0; t < T + 2; t++) {
            asm volatile("bar.sync %0, 96;" :: "r"(barid) : "memory");

            if (t < T) {
                if (t + 8 < T)
                    cp16(dst0 + ((t + 8) & 7) * 512, srcb + (long long)(t + 8) * G);
                CP_COMMIT();
                CP_WAIT7();
                float4 xg = xqs[el][t & 7][uu];   // conflict-free LDS.128

                const float4* hp = reinterpret_cast<const float4*>(se[el].h1[(t + 1) & 1]);
                float2 e0 = make_float2(xg.x, 0.f), o0 = make_float2(0.f, 0.f);
                float2 e1 = make_float2(xg.y, 0.f), o1 = o0;
                float2 e2 = make_float2(xg.z, 0.f), o2 = o0;
                float2 e3 = make_float2(xg.w, 0.f), o3 = o0;
                #pragma unroll
                for (int jq = 0; jq < 7; jq++) {
                    float4 h4 = hp[jq];               // broadcast LDS.128
                    float2 p0 = make_float2(h4.x, h4.y);
                    float2 p1 = make_float2(h4.z, h4.w);
                    e0 = ffma2(p0, wh[0][2 * jq], e0);
                    e1 = ffma2(p0, wh[1][2 * jq], e1);
                    e2 = ffma2(p0, wh[2][2 * jq], e2);
                    e3 = ffma2(p0, wh[3][2 * jq], e3);
                    if (2 * jq + 1 < 13) {
                        o0 = ffma2(p1, wh[0][2 * jq + 1], o0);
                        o1 = ffma2(p1, wh[1][2 * jq + 1], o1);
                        o2 = ffma2(p1, wh[2][2 * jq + 1], o2);
                        o3 = ffma2(p1, wh[3][2 * jq + 1], o3);
                    }
                }
                float gi = sigm  ((e0.x + e0.y) + (o0.x + o0.y));
                float gf = sigm  ((e1.x + e1.y) + (o1.x + o1.y));
                float gg = tanh_f((e2.x + e2.y) + (o2.x + o2.y));
                float go = sigm  ((e3.x + e3.y) + (o3.x + o3.y));
                c1 = fmaf(gf, c1, gi * gg);
                float h1v = go * tanh_f(c1);
                if (lane < 25) se[el].h1[t & 1][lane] = h1v;
            }
            __syncwarp();
        }
    } else if (role == 2) {
        // ================= Warp C: L2 input projection (lag 1) =================
        float2 wx[4][13];   // wx[g][12].y = bias (pairs h1[25]=1)
        #pragma unroll
        for (int g = 0; g < 4; g++) {
            const float* WX = (g == 0) ? Wxi2 : (g == 1) ? Wxf2 : (g == 2) ? Wxc2 : Wxo2;
            const float* BB = (g == 0) ? bi2  : (g == 1) ? bf2  : (g == 2) ? bc2  : bo2;
            #pragma unroll
            for (int jp = 0; jp < 13; jp++) {
                int j0 = 2 * jp, j1 = 2 * jp + 1;
                wx[g][jp].x = WX[j0 * 25 + uu];
                wx[g][jp].y = (j1 < 25) ? WX[j1 * 25 + uu] : ((j1 == 25) ? BB[uu] : 0.f);
            }
        }

        #pragma unroll 2
        for (int t = 0; t < T + 2; t++) {
            asm volatile("bar.sync %0, 96;" :: "r"(barid) : "memory");

            if (t >= 1 && t <= T) {
                const int s1 = t - 1;
                const float4* hp = reinterpret_cast<const float4*>(se[el].h1[s1 & 1]);
                float2 e0 = make_float2(0.f, 0.f), o0 = e0;
                float2 e1 = e0, o1 = e0, e2 = e0, o2 = e0, e3 = e0, o3 = e0;
                #pragma unroll
                for (int jq = 0; jq < 7; jq++) {
                    float4 h4 = hp[jq];               // broadcast LDS.128
                    float2 p0 = make_float2(h4.x, h4.y);
                    float2 p1 = make_float2(h4.z, h4.w);
                    e0 = ffma2(p0, wx[0][2 * jq], e0);
                    e1 = ffma2(p0, wx[1][2 * jq], e1);
                    e2 = ffma2(p0, wx[2][2 * jq], e2);
                    e3 = ffma2(p0, wx[3][2 * jq], e3);
                    if (2 * jq + 1 < 13) {
                        o0 = ffma2(p1, wx[0][2 * jq + 1], o0);
                        o1 = ffma2(p1, wx[1][2 * jq + 1], o1);
                        o2 = ffma2(p1, wx[2][2 * jq + 1], o2);
                        o3 = ffma2(p1, wx[3][2 * jq + 1], o3);
                    }
                }
                if (lane < 25)
                    se[el].zx[s1 & 1][lane] = make_float4(
                        (e0.x + e0.y) + (o0.x + o0.y),
                        (e1.x + e1.y) + (o1.x + o1.y),
                        (e2.x + e2.y) + (o2.x + o2.y),
                        (e3.x + e3.y) + (o3.x + o3.y));
            }
            __syncwarp();
        }
    } else {
        // ================= Warp B: L2 recurrence (lag 2) =================
        float2 wh[4][13];
        #pragma unroll
        for (int g = 0; g < 4; g++) {
            const float* W2 = (g == 0) ? Whi2 : (g == 1) ? Whf2 : (g == 2) ? Whc2 : Who2;
            #pragma unroll
            for (int jp = 0; jp < 13; jp++) {
                int j0 = 2 * jp, j1 = 2 * jp + 1;
                wh[g][jp].x = W2[j0 * 25 + uu];
                wh[g][jp].y = (j1 < 25) ? W2[j1 * 25 + uu] : 0.f;
            }
        }
        float c2 = 0.f;

        #pragma unroll 2
        for (int t = 0; t < T + 2; t++) {
            asm volatile("bar.sync %0, 96;" :: "r"(barid) : "memory");

            if (t >= 2) {          // t <= T+1 by loop bound; s = t-2 in [0, T-1]
                const int s = t - 2;
                float4 zq = se[el].zx[s & 1][uu];     // lane-distinct LDS.128
                const float4* gp = reinterpret_cast<const float4*>(se[el].h2[(s + 1) & 1]);
                float2 e0 = make_float2(zq.x, 0.f), o0 = make_float2(0.f, 0.f);
                float2 e1 = make_float2(zq.y, 0.f), o1 = o0;
                float2 e2 = make_float2(zq.z, 0.f), o2 = o0;
                float2 e3 = make_float2(zq.w, 0.f), o3 = o0;
                #pragma unroll
                for (int jq = 0; jq < 7; jq++) {
                    float4 g4 = gp[jq];               // broadcast LDS.128
                    float2 r0 = make_float2(g4.x, g4.y);
                    float2 r1 = make_float2(g4.z, g4.w);
                    e0 = ffma2(r0, wh[0][2 * jq], e0);
                    e1 = ffma2(r0, wh[1][2 * jq], e1);
                    e2 = ffma2(r0, wh[2][2 * jq], e2);
                    e3 = ffma2(r0, wh[3][2 * jq], e3);
                    if (2 * jq + 1 < 13) {
                        o0 = ffma2(r1, wh[0][2 * jq + 1], o0);
                        o1 = ffma2(r1, wh[1][2 * jq + 1], o1);
                        o2 = ffma2(r1, wh[2][2 * jq + 1], o2);
                        o3 = ffma2(r1, wh[3][2 * jq + 1], o3);
                    }
                }
                float hi = sigm  ((e0.x + e0.y) + (o0.x + o0.y));
                float hf = sigm  ((e1.x + e1.y) + (o1.x + o1.y));
                float hg = tanh_f((e2.x + e2.y) + (o2.x + o2.y));
                float ho = sigm  ((e3.x + e3.y) + (o3.x + o3.y));
                c2 = fmaf(hf, c2, hi * hg);
                float h2v = ho * tanh_f(c2);
                if (lane < 25) {
                    se[el].h2[s & 1][lane] = h2v;
                    g_h2[(bT + s) * 32 + lane] = h2v;   // stream for head kernel
                }
            }
            __syncwarp();
        }
    }
}

// ---------------------------------------------------------------------------
// Kernel 3: output head.  out[row] = sigm(dot(g_h2[row][0:25], Wout) + bout)
// ---------------------------------------------------------------------------
__global__ __launch_bounds__(256) void head_kernel(
    const float* __restrict__ Wout, const float* __restrict__ bout,
    float* __restrict__ out)
{
    __shared__ float hs[256][33];
    __shared__ float wo[26];

    const int tid = threadIdx.x;
    const long long row0 = (long long)blockIdx.x * 256;

    if (tid < 25) wo[tid] = Wout[tid];
    if (tid == 25) wo[25] = bout[0];

    for (int idx = tid; idx < 256 * 8; idx += 256) {
        int r = idx >> 3, q = idx & 7;
        float4 v = *reinterpret_cast<const float4*>(&g_h2[(row0 + r) * 32 + q * 4]);
        hs[r][q * 4 + 0] = v.x;
        hs[r][q * 4 + 1] = v.y;
        hs[r][q * 4 + 2] = v.z;
        hs[r][q * 4 + 3] = v.w;
    }
    __syncthreads();

    float acc = wo[25];
    #pragma unroll
    for (int j = 0; j < 25; j++) acc = fmaf(hs[tid][j], wo[j], acc);
    out[row0 + tid] = sigm(acc);
}

// ---------------------------------------------------------------------------
// Host launcher. Input order detected from in_sizes (validated R3..R16):
//   dict order      : x, Wout(25), bout(1), l1_*(12), l2_*(12)
//   signature order : x, l1_*(12), l2_*(12), Wout, bout
// Per-layer order: Wxi, bi, Whi, Wxf, bf, Whf, Wxc, bc, Whc, Wxo, bo, Who
// ---------------------------------------------------------------------------
extern "C" void kernel_launch(void* const* d_in, const int* in_sizes, int n_in,
                              void* d_out, int out_size) {
    const float* p[27];
    for (int i = 0; i < 27 && i < n_in; i++) p[i] = (const float*)d_in[i];
    const float* x = p[0];

    int l1, l2, iWout, ibout;
    if (n_in >= 3 && in_sizes[1] == H) {   // dict order (Wout right after x)
        iWout = 1; ibout = 2; l1 = 3; l2 = 15;
    } else {                                // reference-signature order
        l1 = 1; l2 = 13; iWout = 25; ibout = 26;
    }

    xproj_kernel<<<(int)(ROWS / XROWS), 256>>>(
        x,
        p[l1 + 0], p[l1 + 1],    // Wxi, bi
        p[l1 + 3], p[l1 + 4],    // Wxf, bf
        p[l1 + 6], p[l1 + 7],    // Wxc, bc
        p[l1 + 9], p[l1 + 10]);  // Wxo, bo

    lstm_kernel<<<B / 2, 192>>>(
        p[l1 + 2], p[l1 + 5], p[l1 + 8], p[l1 + 11],     // l1 Whi, Whf, Whc, Who
        p[l2 + 0], p[l2 + 3], p[l2 + 6], p[l2 + 9],      // l2 Wxi, Wxf, Wxc, Wxo
        p[l2 + 1], p[l2 + 4], p[l2 + 7], p[l2 + 10],     // l2 bi, bf, bc, bo
        p[l2 + 2], p[l2 + 5], p[l2 + 8], p[l2 + 11]);    // l2 Whi, Whf, Whc, Who

    head_kernel<<<(int)(ROWS / 256), 256>>>(p[iWout], p[ibout], (float*)d_out);
}